// round 1
// baseline (speedup 1.0000x reference)
#include <cuda_runtime.h>
#include <cuda_bf16.h>

#define NCI 16
#define NCO 32
#define NBR 3
#define NTERM (NCI * 9 * NBR)   // 432
#define HH 32
#define WW 32
#define NBATCH 4

__device__ float4 g_A[NCO * NTERM];
__device__ float  g_C[NCO * NTERM];
__device__ float  g_bc[NCO];

__device__ __forceinline__ float tanh_approx(float x) {
    float y;
    asm("tanh.approx.f32 %0, %1;" : "=f"(y) : "f"(x));
    return y;
}

// One block per co. Packs per-term constants and reduces the position-independent
// bias term  sum(coef*bias) + out_bias.
__global__ void prep_kernel(const float* __restrict__ k,
                            const float* __restrict__ Ec,
                            const float* __restrict__ Ps,
                            const float* __restrict__ bias,
                            const float* __restrict__ coef,
                            const float* __restrict__ out_bias) {
    int co  = blockIdx.x;
    int tid = threadIdx.x;
    float cb = 0.0f;
    for (int p = tid; p < NTERM; p += blockDim.x) {
        // packed term order within co:  p = (ci*9 + ij)*3 + nb
        int nb = p % 3;
        int ij = (p / 3) % 9;
        int ci = p / 27;
        // raw layout: [co][ci][nb][i][j]
        int raw = (((co * NCI + ci) * NBR + nb) * 9) + ij;
        float kk = k[raw];
        float e  = Ec[raw];
        float ps = Ps[raw];
        float bb = bias[raw];
        float cc = coef[raw];
        float4 a;
        a.x = 5.0f * e;          // Ec5  (tanh arg1 = 5x + 5Ec)
        a.y = kk;                // k
        a.z = 0.9f * kk * e;     // k*Ec*0.9
        a.w = 0.1f * kk * e;     // k*Ec*0.1
        g_A[co * NTERM + p] = a;
        g_C[co * NTERM + p] = cc * ps;
        cb += cc * bb;
    }
    __shared__ float red[128];
    red[tid] = cb;
    __syncthreads();
    for (int s = 64; s > 0; s >>= 1) {
        if (tid < s) red[tid] += red[tid + s];
        __syncthreads();
    }
    if (tid == 0) g_bc[co] = red[0] + out_bias[co];
}

// Block = (b, co, 4-row tile). 128 threads = 32 cols x 4 rows, one output each.
__global__ __launch_bounds__(128)
void ferro_main_kernel(const float* __restrict__ x, float* __restrict__ out) {
    __shared__ float4 sA[NTERM];
    __shared__ float  sC[NTERM];
    __shared__ float  sx[NCI][6][34];   // 6 input rows, 34 cols (1-col zero pad each side)

    int tid  = threadIdx.x;
    int tile = blockIdx.x & 7;           // 8 tiles of 4 output rows
    int co   = (blockIdx.x >> 3) & 31;
    int b    = blockIdx.x >> 8;
    int r0   = tile * 4;

    // stage packed params (broadcast-friendly smem)
    for (int p = tid; p < NTERM; p += 128) {
        sA[p] = g_A[co * NTERM + p];
        sC[p] = g_C[co * NTERM + p];
    }
    // zero the horizontal pad columns
    for (int idx = tid; idx < NCI * 6; idx += 128) {
        int ci = idx / 6, rr = idx % 6;
        sx[ci][rr][0]  = 0.0f;
        sx[ci][rr][33] = 0.0f;
    }
    // load interior (rows outside [0,32) -> zero)
    for (int idx = tid; idx < NCI * 6 * 32; idx += 128) {
        int c  = idx & 31;
        int rr = (idx >> 5) % 6;
        int ci = idx / (6 * 32);
        int gr = r0 - 1 + rr;
        float v = 0.0f;
        if ((unsigned)gr < 32u) v = x[((b * NCI + ci) * HH + gr) * WW + c];
        sx[ci][rr][c + 1] = v;
    }
    __syncthreads();

    int wo = tid & 31;   // lane = output col -> conflict-free smem rows
    int lr = tid >> 5;   // 0..3 local output row

    float acc0 = 0.0f, acc1 = 0.0f, acc2 = 0.0f;

    #pragma unroll 1
    for (int ci = 0; ci < NCI; ci++) {
        float xv[9];
        #pragma unroll
        for (int dy = 0; dy < 3; dy++)
            #pragma unroll
            for (int dx = 0; dx < 3; dx++)
                xv[dy * 3 + dx] = sx[ci][lr + dy][wo + dx];

        int base = ci * 27;
        #pragma unroll
        for (int ij = 0; ij < 9; ij++) {
            float xx = xv[ij];
            #pragma unroll
            for (int nb = 0; nb < 3; nb++) {
                float4 a  = sA[base + ij * 3 + nb];
                float  cp = sC[base + ij * 3 + nb];
                // t1 = tanh(5(x+Ec))
                float t1 = tanh_approx(fmaf(5.0f, xx, a.x));
                // arg2 = k*x + 0.9*k*Ec + 0.1*k*Ec*t1
                float arg2 = fmaf(a.w, t1, fmaf(a.y, xx, a.z));
                float t2 = tanh_approx(arg2);
                if (nb == 0)      acc0 = fmaf(cp, t2, acc0);
                else if (nb == 1) acc1 = fmaf(cp, t2, acc1);
                else              acc2 = fmaf(cp, t2, acc2);
            }
        }
    }

    float res = (acc0 + acc1) + (acc2 + g_bc[co]);
    int ho = r0 + lr;
    out[((b * NCO + co) * HH + ho) * WW + wo] = res;
}

extern "C" void kernel_launch(void* const* d_in, const int* in_sizes, int n_in,
                              void* d_out, int out_size) {
    const float* x        = (const float*)d_in[0];
    const float* k        = (const float*)d_in[1];
    const float* Ec       = (const float*)d_in[2];
    const float* Ps       = (const float*)d_in[3];
    const float* bias     = (const float*)d_in[4];
    const float* coef     = (const float*)d_in[5];
    const float* out_bias = (const float*)d_in[6];
    float* out = (float*)d_out;

    prep_kernel<<<NCO, 128>>>(k, Ec, Ps, bias, coef, out_bias);
    ferro_main_kernel<<<NBATCH * NCO * 8, 128>>>(x, out);
}